// round 12
// baseline (speedup 1.0000x reference)
#include <cuda_runtime.h>

// Persistent neural-CDE kernel, warp-specialized counter-phase pipeline.
// 128 CTAs x 416 threads. CTA r owns batch row r and W3 col-slice h=r.
// Rows split into group A (0-63) / B (64-127). Warps 0-3: row crew
// (RK4 + gemv + publish). Warps 4-11: GEMM crew (half-GEMMs A,B per stage).
// Warp 12 of CTA0: sync hub (aggregates ready flags -> go flags).
// While GEMM crews compute group A, group B row crews advance, and v.v.

#define NCTAS   128
#define NT      416
#define NSTAGES 256

typedef unsigned long long u64;
typedef unsigned int u32;

__device__ float g_h2buf[2][128][64];   // [g][k][rowInGroup]
__device__ float g_dzbuf[2][64][128];   // [g][rowInGroup][h]
__device__ float g_dx[128 * 3 * 32];    // [globalRow][sel][c]
__device__ u32 g_h2rdy[128 * 8];        // per-CTA h2 ready counters (32B stride)
__device__ u32 g_dzrdy[128 * 8];        // per-CTA dz ready counters
__device__ u32 g_go[4 * 8];             // [h2goA, h2goB, dzgoA, dzgoB]
__device__ u32 g_slot[128];             // calibration barrier
__device__ u32 g_gen;

__device__ __forceinline__ u32 ld_rlx(const u32* p) {
    u32 v;
    asm volatile("ld.relaxed.gpu.b32 %0, [%1];" : "=r"(v) : "l"(p) : "memory");
    return v;
}
__device__ __forceinline__ void st_rel(u32* p, u32 v) {
    asm volatile("st.release.gpu.b32 [%0], %1;" :: "l"(p), "r"(v) : "memory");
}
__device__ __forceinline__ void fence_acqrel() {
    asm volatile("fence.acq_rel.gpu;" ::: "memory");
}
#define BAR1() asm volatile("bar.sync 1, 128;" ::: "memory")
#define BAR2() asm volatile("bar.sync 2, 256;" ::: "memory")

// calibration grid barrier (hub pattern, all 416 threads participate)
__device__ __forceinline__ void grid_barrier(u32 target)
{
    __syncthreads();
    if (blockIdx.x == 0) {
        if (threadIdx.x < 32) {
            if (threadIdx.x == 0) {
                __threadfence();
                st_rel(g_slot, target);
            }
            const u32* p = g_slot + threadIdx.x * 4;
            u32 a, b, c, d; bool ok;
            do {
                asm volatile("ld.relaxed.gpu.v4.b32 {%0,%1,%2,%3}, [%4];"
                             : "=r"(a), "=r"(b), "=r"(c), "=r"(d) : "l"(p) : "memory");
                ok = (a == target) && (b == target) && (c == target) && (d == target);
            } while (!__all_sync(0xffffffffu, ok));
            if (threadIdx.x == 0) {
                fence_acqrel();
                asm volatile("st.relaxed.gpu.b32 [%0], %1;" :: "l"(&g_gen), "r"(target) : "memory");
            }
        }
    } else {
        if (threadIdx.x == 0) {
            __threadfence();
            st_rel(g_slot + blockIdx.x, target);
            u32 g;
            do {
                asm volatile("ld.acquire.gpu.b32 %0, [%1];" : "=r"(g) : "l"(&g_gen) : "memory");
            } while (g != target);
        }
    }
    __syncthreads();
}

// wait until *p - target >= 0 (monotonic), then IVALL-fence
__device__ __forceinline__ void poll_ge(const u32* p, u32 target)
{
    u32 v;
    do { v = ld_rlx(p); } while ((int)(v - target) < 0);
    fence_acqrel();
}

// cephes-style rational tanh (UNCHANGED numerics)
__device__ __forceinline__ float tanh_pq(float x, float& qo)
{
    x = fminf(fmaxf(x, -7.90531110591164f), 7.90531110591164f);
    float x2 = x * x;
    float p = fmaf(x2, -2.76076847742355e-16f, 2.00018790482477e-13f);
    p = fmaf(p, x2, -8.60467152213735e-11f);
    p = fmaf(p, x2,  5.12229709037114e-08f);
    p = fmaf(p, x2,  1.48572235717979e-05f);
    p = fmaf(p, x2,  6.37261928875436e-04f);
    p = fmaf(p, x2,  4.89352455891786e-03f);
    p = p * x;
    float q = fmaf(x2, 1.19825839466702e-06f, 1.18534705686654e-04f);
    q = fmaf(q, x2, 2.26843463243900e-03f);
    qo = fmaf(q, x2, 4.89352518554385e-03f);
    return p;
}
__device__ __forceinline__ void rcp4(const float* q, float* inv)
{
    float a01 = q[0] * q[1], a23 = q[2] * q[3], P = a01 * a23, R;
    asm("rcp.approx.f32 %0, %1;" : "=f"(R) : "f"(P));
    inv[0] = R * q[1] * a23;
    inv[1] = R * q[0] * a23;
    inv[2] = R * a01 * q[3];
    inv[3] = R * a01 * q[2];
}

// smem: w1s 16384 | w2s 16384 | w3s 4096 | b1s,b2s,ys,zs,kacc,h1s 6*128 | misc
#define SMEM_FLOATS (16384*2 + 4096 + 6*128 + 16)
#define SMEM_BYTES  (SMEM_FLOATS * 4)

extern __shared__ float smem[];

__global__ __launch_bounds__(NT, 1)
void cde_kernel(const float* __restrict__ coeffs,
                const float* __restrict__ W1, const float* __restrict__ b1,
                const float* __restrict__ W2, const float* __restrict__ b2,
                const float* __restrict__ W3, const float* __restrict__ b3,
                const float* __restrict__ Wi, const float* __restrict__ bi,
                const float* __restrict__ Wr, const float* __restrict__ br,
                float* __restrict__ out)
{
    float* w1s  = smem;
    float* w2s  = w1s + 16384;
    float* w3s  = w2s + 16384;          // [k][c] 128x32
    float* b1s  = w3s + 4096;
    float* b2s  = b1s + 128;
    float* ys   = b2s + 128;
    float* zs   = ys  + 128;
    float* kacc = zs  + 128;
    float* h1s  = kacc + 128;
    u32* sb     = (u32*)(h1s + 128);

    const int tid = threadIdx.x;
    const int wid = tid >> 5;
    const int r   = blockIdx.x;
    const int grp = r >> 6;             // 0 = rows 0-63, 1 = rows 64-127
    const int rIdx = r & 63;

    // ---- prologue: weights + z0 ----
    for (int i = tid; i < 4096; i += NT) {
        ((float4*)w1s)[i] = ((const float4*)W1)[i];
        ((float4*)w2s)[i] = ((const float4*)W2)[i];
    }
    for (int i = tid; i < 1024; i += NT) {
        int k = i >> 3, cq = i & 7;
        *(float4*)(w3s + k * 32 + cq * 4) =
            *(const float4*)(W3 + k * 4096 + r * 32 + cq * 4);
    }
    if (tid < 128) { b1s[tid] = b1[tid]; b2s[tid] = b2[tid]; }
    if (tid < 128) {
        const float* ca = coeffs + (size_t)r * 8192;
        float acc = bi[tid];
        #pragma unroll
        for (int c = 0; c < 32; c++)
            acc = fmaf(ca[c], Wi[c * 128 + tid], acc);
        zs[tid] = acc; ys[tid] = acc; kacc[tid] = 0.0f;
    }
    if (tid == 0) sb[0] = ld_rlx(&g_gen);
    __syncthreads();

    const u32 gb = sb[0];
    grid_barrier(gb + 1);

    // ---- base-read window (all semaphores quiescent here) ----
    u32 h2rdy_b = 0, dzgo_b = 0;                  // row crew tid 0
    u32 h2go_b0 = 0, h2go_b1 = 0, dzrdy_b = 0;    // gemm crew tid 128
    u32 agA0 = 0, agA1 = 0, agB0 = 0, agB1 = 0;   // hub lanes
    u32 agD0 = 0, agD1 = 0, agD2 = 0, agD3 = 0;
    u32 aggo0 = 0, aggo1 = 0, aggo2 = 0, aggo3 = 0;
    if (tid == 0) {
        h2rdy_b = ld_rlx(g_h2rdy + r * 8);
        dzgo_b  = ld_rlx(g_go + (2 + grp) * 8);
    }
    if (tid == 128) {
        h2go_b0 = ld_rlx(g_go + 0 * 8);
        h2go_b1 = ld_rlx(g_go + 1 * 8);
        dzrdy_b = ld_rlx(g_dzrdy + r * 8);
    }
    if (wid == 12 && r == 0) {
        int lane = tid & 31;
        agA0 = ld_rlx(g_h2rdy + (lane * 2 + 0) * 8);
        agA1 = ld_rlx(g_h2rdy + (lane * 2 + 1) * 8);
        agB0 = ld_rlx(g_h2rdy + (64 + lane * 2 + 0) * 8);
        agB1 = ld_rlx(g_h2rdy + (64 + lane * 2 + 1) * 8);
        agD0 = ld_rlx(g_dzrdy + (lane * 4 + 0) * 8);
        agD1 = ld_rlx(g_dzrdy + (lane * 4 + 1) * 8);
        agD2 = ld_rlx(g_dzrdy + (lane * 4 + 2) * 8);
        agD3 = ld_rlx(g_dzrdy + (lane * 4 + 3) * 8);
        aggo0 = ld_rlx(g_go + 0 * 8); aggo1 = ld_rlx(g_go + 1 * 8);
        aggo2 = ld_rlx(g_go + 2 * 8); aggo3 = ld_rlx(g_go + 3 * 8);
    }
    grid_barrier(gb + 2);

    // ================= role dispatch (no __syncthreads below) =================

    if (wid < 4) {
        // ---------------- ROW CREW (threads 0..127) ----------------
        const int j = tid;
        for (int t = 0; t < NSTAGES; ++t) {
            const int stage = t & 3;
            if (t > 0) {
                if (j == 0) poll_ge(g_go + (2 + grp) * 8, dzgo_b + (u32)t);
                BAR1();
                const int ps = (t - 1) & 3;      // apply dz of previous stage
                float dz = g_dzbuf[grp][rIdx][j];
                float kv = kacc[j] + ((ps == 0 || ps == 3) ? 1.0f : 2.0f) * dz;
                if (ps < 3) {
                    ys[j] = zs[j] + ((ps == 2) ? 1.0f : 0.5f) * dz;
                    kacc[j] = kv;
                } else {
                    float zn = fmaf(1.0f / 6.0f, kv, zs[j]);
                    zs[j] = zn; ys[j] = zn; kacc[j] = 0.0f;
                }
                BAR1();
            }
            // gemv1: h1 = relu(ys @ W1 + b1), thread j = full column
            {
                float a0 = 0.f, a1 = 0.f;
                #pragma unroll 8
                for (int k = 0; k < 128; k += 2) {
                    a0 = fmaf(ys[k],     w1s[ k      * 128 + j], a0);
                    a1 = fmaf(ys[k + 1], w1s[(k + 1) * 128 + j], a1);
                }
                h1s[j] = fmaxf(a0 + a1 + b1s[j], 0.0f);
            }
            BAR1();
            // gemv2: h2 = relu(h1 @ W2 + b2), publish straight to global
            {
                float a0 = 0.f, a1 = 0.f;
                #pragma unroll 8
                for (int k = 0; k < 128; k += 2) {
                    a0 = fmaf(h1s[k],     w2s[ k      * 128 + j], a0);
                    a1 = fmaf(h1s[k + 1], w2s[(k + 1) * 128 + j], a1);
                }
                g_h2buf[grp][j][rIdx] = fmaxf(a0 + a1 + b2s[j], 0.0f);
            }
            if (stage == 0 && j < 32) {          // publish dX for this segment
                const int s = t >> 2;
                const float* bc = coeffs + (size_t)r * 8192 + s * 128;
                float cb = bc[32 + j], c2 = bc[64 + j], c3 = bc[96 + j];
                g_dx[(r * 3 + 0) * 32 + j] = cb;
                g_dx[(r * 3 + 1) * 32 + j] = fmaf(0.25f, c3, fmaf(0.5f, c2, cb));
                g_dx[(r * 3 + 2) * 32 + j] = (s < 63) ? bc[128 + 32 + j]
                                                      : (cb + c2 + c3);
            }
            BAR1();
            if (j == 0) {
                __threadfence();
                st_rel(g_h2rdy + r * 8, h2rdy_b + (u32)(t + 1));
            }
        }
        // final RK4 (dz of stage 255, ps = 3)
        if (j == 0) poll_ge(g_go + (2 + grp) * 8, dzgo_b + (u32)NSTAGES);
        BAR1();
        {
            float dz = g_dzbuf[grp][rIdx][j];
            float kv = kacc[j] + 1.0f * dz;
            zs[j] = fmaf(1.0f / 6.0f, kv, zs[j]);
        }
        BAR1();
        // readout
        if (tid < 32) {
            float part = 0.0f;
            #pragma unroll
            for (int h = tid; h < 128; h += 32)
                part = fmaf(zs[h], Wr[h], part);
            #pragma unroll
            for (int off = 16; off >= 1; off >>= 1)
                part += __shfl_down_sync(0xffffffffu, part, off);
            if (tid == 0)
                out[r] = 1.0f / (1.0f + __expf(-(part + br[0])));
        }
    } else if (wid < 12) {
        // ---------------- GEMM CREW (threads 128..383) ----------------
        const int ct = tid - 128;                // 0..255
        const int cg = ct & 7, rg = ct >> 3;     // 32 row-pairs x 8 col-quads
        const int r0 = rg << 1;
        const float4 b3q = *(const float4*)(b3 + r * 32 + (cg << 2));
        u64 B01, B23;
        asm("mov.b64 %0, {%1,%2};" : "=l"(B01) : "f"(b3q.x), "f"(b3q.y));
        asm("mov.b64 %0, {%1,%2};" : "=l"(B23) : "f"(b3q.z), "f"(b3q.w));
        const float* ws = w3s + (cg << 2);

        for (int t = 0; t < NSTAGES; ++t) {
            const int stage = t & 3;
            const int sel = (stage == 0) ? 0 : ((stage == 3) ? 2 : 1);
            #pragma unroll 1
            for (int gg = 0; gg < 2; ++gg) {
                if (ct == 0)
                    poll_ge(g_go + gg * 8,
                            (gg ? h2go_b1 : h2go_b0) + (u32)(t + 1));
                BAR2();
                const int grow = gg * 64 + r0;
                float4 dA = *(const float4*)(g_dx + (grow * 3 + sel) * 32 + (cg << 2));
                float4 dB = *(const float4*)(g_dx + ((grow + 1) * 3 + sel) * 32 + (cg << 2));
                const float* hg = &g_h2buf[gg][0][r0];   // stride 64 per k

                u64 A01 = B01, A23 = B23, E01 = B01, E23 = B23;
                {
                    float2 hb0[8], hb1[8];
                    #pragma unroll
                    for (int kk = 0; kk < 8; kk++)
                        hb0[kk] = *(const float2*)(hg + kk * 64);
                    #pragma unroll 2
                    for (int blk = 0; blk < 16; blk++) {
                        float2* cur = (blk & 1) ? hb1 : hb0;
                        float2* nxt = (blk & 1) ? hb0 : hb1;
                        const float* hnx = hg + (blk + 1) * 512;
                        const float* wb  = ws + blk * 256;
                        #pragma unroll
                        for (int kk = 0; kk < 8; kk++) {
                            if (blk < 15)
                                nxt[kk] = *(const float2*)(hnx + kk * 64);
                            float2 h = cur[kk];
                            float4 w = *(const float4*)(wb + kk * 32);
                            u64 w01, w23, hx2, hy2;
                            asm("mov.b64 %0, {%1,%2};" : "=l"(w01) : "f"(w.x), "f"(w.y));
                            asm("mov.b64 %0, {%1,%2};" : "=l"(w23) : "f"(w.z), "f"(w.w));
                            asm("mov.b64 %0, {%1,%1};" : "=l"(hx2) : "f"(h.x));
                            asm("mov.b64 %0, {%1,%1};" : "=l"(hy2) : "f"(h.y));
                            asm("fma.rn.f32x2 %0,%1,%2,%0;" : "+l"(A01) : "l"(w01), "l"(hx2));
                            asm("fma.rn.f32x2 %0,%1,%2,%0;" : "+l"(A23) : "l"(w23), "l"(hx2));
                            asm("fma.rn.f32x2 %0,%1,%2,%0;" : "+l"(E01) : "l"(w01), "l"(hy2));
                            asm("fma.rn.f32x2 %0,%1,%2,%0;" : "+l"(E23) : "l"(w23), "l"(hy2));
                        }
                    }
                }
                float a0, a1, a2, a3, e0, e1, e2, e3;
                asm("mov.b64 {%0,%1}, %2;" : "=f"(a0), "=f"(a1) : "l"(A01));
                asm("mov.b64 {%0,%1}, %2;" : "=f"(a2), "=f"(a3) : "l"(A23));
                asm("mov.b64 {%0,%1}, %2;" : "=f"(e0), "=f"(e1) : "l"(E01));
                asm("mov.b64 {%0,%1}, %2;" : "=f"(e2), "=f"(e3) : "l"(E23));

                float p[8], q[8], inv[8];
                p[0] = tanh_pq(a0, q[0]); p[1] = tanh_pq(a1, q[1]);
                p[2] = tanh_pq(a2, q[2]); p[3] = tanh_pq(a3, q[3]);
                p[4] = tanh_pq(e0, q[4]); p[5] = tanh_pq(e1, q[5]);
                p[6] = tanh_pq(e2, q[6]); p[7] = tanh_pq(e3, q[7]);
                rcp4(q, inv); rcp4(q + 4, inv + 4);

                float pr0 = p[0]*inv[0]*dA.x + p[1]*inv[1]*dA.y
                          + p[2]*inv[2]*dA.z + p[3]*inv[3]*dA.w;
                float pr1 = p[4]*inv[4]*dB.x + p[5]*inv[5]*dB.y
                          + p[6]*inv[6]*dB.z + p[7]*inv[7]*dB.w;
                #pragma unroll
                for (int off = 4; off >= 1; off >>= 1) {
                    pr0 += __shfl_down_sync(0xffffffffu, pr0, off);
                    pr1 += __shfl_down_sync(0xffffffffu, pr1, off);
                }
                if (cg == 0) {
                    g_dzbuf[gg][r0    ][r] = pr0;
                    g_dzbuf[gg][r0 + 1][r] = pr1;
                }
                BAR2();
                if (ct == 0) {
                    __threadfence();
                    st_rel(g_dzrdy + r * 8, dzrdy_b + (u32)(2 * t + gg + 1));
                }
            }
        }
    } else if (r == 0) {
        // ---------------- SYNC HUB (CTA0, warp 12) ----------------
        const int lane = tid & 31;
        const u32* pA0 = g_h2rdy + (lane * 2 + 0) * 8;
        const u32* pA1 = g_h2rdy + (lane * 2 + 1) * 8;
        const u32* pB0 = g_h2rdy + (64 + lane * 2 + 0) * 8;
        const u32* pB1 = g_h2rdy + (64 + lane * 2 + 1) * 8;
        const u32* pD0 = g_dzrdy + (lane * 4 + 0) * 8;
        const u32* pD1 = g_dzrdy + (lane * 4 + 1) * 8;
        const u32* pD2 = g_dzrdy + (lane * 4 + 2) * 8;
        const u32* pD3 = g_dzrdy + (lane * 4 + 3) * 8;
        for (int t = 0; t < NSTAGES; ++t) {
            const u32 tv = (u32)(t + 1);
            bool ok;
            do {    // group A h2
                u32 a = ld_rlx(pA0), b = ld_rlx(pA1);
                ok = ((int)(a - (agA0 + tv)) >= 0) && ((int)(b - (agA1 + tv)) >= 0);
            } while (!__all_sync(0xffffffffu, ok));
            if (lane == 0) { fence_acqrel(); st_rel(g_go + 0 * 8, aggo0 + tv); }
            do {    // group B h2
                u32 a = ld_rlx(pB0), b = ld_rlx(pB1);
                ok = ((int)(a - (agB0 + tv)) >= 0) && ((int)(b - (agB1 + tv)) >= 0);
            } while (!__all_sync(0xffffffffu, ok));
            if (lane == 0) { fence_acqrel(); st_rel(g_go + 1 * 8, aggo1 + tv); }
            {   // dz group A: dzrdy >= 2t+1
                const u32 dv = (u32)(2 * t + 1);
                do {
                    u32 a = ld_rlx(pD0), b = ld_rlx(pD1);
                    u32 c = ld_rlx(pD2), d = ld_rlx(pD3);
                    ok = ((int)(a - (agD0 + dv)) >= 0) && ((int)(b - (agD1 + dv)) >= 0)
                      && ((int)(c - (agD2 + dv)) >= 0) && ((int)(d - (agD3 + dv)) >= 0);
                } while (!__all_sync(0xffffffffu, ok));
                if (lane == 0) { fence_acqrel(); st_rel(g_go + 2 * 8, aggo2 + tv); }
            }
            {   // dz group B: dzrdy >= 2t+2
                const u32 dv = (u32)(2 * t + 2);
                do {
                    u32 a = ld_rlx(pD0), b = ld_rlx(pD1);
                    u32 c = ld_rlx(pD2), d = ld_rlx(pD3);
                    ok = ((int)(a - (agD0 + dv)) >= 0) && ((int)(b - (agD1 + dv)) >= 0)
                      && ((int)(c - (agD2 + dv)) >= 0) && ((int)(d - (agD3 + dv)) >= 0);
                } while (!__all_sync(0xffffffffu, ok));
                if (lane == 0) { fence_acqrel(); st_rel(g_go + 3 * 8, aggo3 + tv); }
            }
        }
    }
    // non-hub warp-12s and finished crews simply exit (named barriers only).
}

extern "C" void kernel_launch(void* const* d_in, const int* in_sizes, int n_in,
                              void* d_out, int out_size)
{
    const float* coeffs = (const float*)d_in[0];
    const float* W1 = (const float*)d_in[1];
    const float* b1 = (const float*)d_in[2];
    const float* W2 = (const float*)d_in[3];
    const float* b2 = (const float*)d_in[4];
    const float* W3 = (const float*)d_in[5];
    const float* b3 = (const float*)d_in[6];
    const float* Wi = (const float*)d_in[7];
    const float* bi = (const float*)d_in[8];
    const float* Wr = (const float*)d_in[9];
    const float* br = (const float*)d_in[10];
    float* out = (float*)d_out;

    cudaFuncSetAttribute(cde_kernel,
                         cudaFuncAttributeMaxDynamicSharedMemorySize, SMEM_BYTES);
    cde_kernel<<<NCTAS, NT, SMEM_BYTES>>>(coeffs, W1, b1, W2, b2, W3, b3,
                                          Wi, bi, Wr, br, out);
}

// round 13
// speedup vs baseline: 1.4305x; 1.4305x over previous
#include <cuda_runtime.h>

// Persistent neural-CDE kernel. 128 CTAs x 512 threads. CTA r owns batch row
// r (gemv/RK4) and W3 column-slice h=r (GEMM). W1/W2/W3-slice in smem.
// R9 champion structure; GEMM h-stream now staged through an 8-deep
// cp.async smem ring (all stages issued upfront, zero register buffers),
// removing the exposed L2 latency of the register double-buffer stream.

#define NCTAS 128
#define NT    512

typedef unsigned long long u64;
typedef unsigned int u32;

__device__ float g_h2T[128 * 128];    // [k][r]
__device__ float g_dz [128 * 128];    // [b][h]
__device__ float g_dx [128 * 3 * 32]; // [b][sel][c]
__device__ u32 g_slot[128];           // per-CTA arrival counters (monotonic)
__device__ u32 g_gen;                 // barrier generation (monotonic)

__device__ __forceinline__ void grid_barrier(u32 target)
{
    __syncthreads();
    if (blockIdx.x == 0) {
        if (threadIdx.x < 32) {
            if (threadIdx.x == 0) {
                __threadfence();   // release our CTA's writes (gpu scope)
                asm volatile("st.release.gpu.b32 [%0], %1;"
                             :: "l"(g_slot), "r"(target) : "memory");
            }
            const u32* p = g_slot + threadIdx.x * 4;
            u32 a, b, c, d; bool ok;
            do {
                asm volatile("ld.relaxed.gpu.v4.b32 {%0,%1,%2,%3}, [%4];"
                             : "=r"(a), "=r"(b), "=r"(c), "=r"(d)
                             : "l"(p) : "memory");
                ok = (a == target) && (b == target) && (c == target) && (d == target);
            } while (!__all_sync(0xffffffffu, ok));
            if (threadIdx.x == 0) {
                asm volatile("fence.acq_rel.gpu;" ::: "memory");
                asm volatile("st.relaxed.gpu.b32 [%0], %1;"
                             :: "l"(&g_gen), "r"(target) : "memory");
            }
        }
    } else {
        if (threadIdx.x == 0) {
            __threadfence();
            asm volatile("st.release.gpu.b32 [%0], %1;"
                         :: "l"(g_slot + blockIdx.x), "r"(target) : "memory");
            u32 g;
            do {
                asm volatile("ld.acquire.gpu.b32 %0, [%1];"
                             : "=r"(g) : "l"(&g_gen) : "memory");
            } while (g != target);
        }
    }
    __syncthreads();
}

// GEMV: out[j] = relu(b[j] + sum_k v[k]*W[k][j]); all operands in smem.
__device__ __forceinline__ void gemv128(const float* __restrict__ vs,
                                        const float* __restrict__ Wsm,
                                        const float* __restrict__ bsm,
                                        float* __restrict__ outv,
                                        float* __restrict__ sp)
{
    const int tid = threadIdx.x;
    const int j = tid & 127, kq = tid >> 7;
    const float* w = Wsm + (kq << 5) * 128 + j;
    const float* v = vs + (kq << 5);
    float acc0 = 0.f, acc1 = 0.f;
    #pragma unroll
    for (int k = 0; k < 32; k += 2) {
        acc0 = fmaf(v[k],     w[ k      * 128], acc0);
        acc1 = fmaf(v[k + 1], w[(k + 1) * 128], acc1);
    }
    sp[(kq << 7) + j] = acc0 + acc1;
    __syncthreads();
    if (tid < 128) {
        float s = bsm[tid] + sp[tid] + sp[128 + tid] + sp[256 + tid] + sp[384 + tid];
        outv[tid] = fmaxf(s, 0.0f);
    }
    __syncthreads();
}

// cephes-style rational tanh: returns p, writes q; tanh(x) = p/q. FMA-only.
__device__ __forceinline__ float tanh_pq(float x, float& qo)
{
    x = fminf(fmaxf(x, -7.90531110591164f), 7.90531110591164f);
    float x2 = x * x;
    float p = fmaf(x2, -2.76076847742355e-16f, 2.00018790482477e-13f);
    p = fmaf(p, x2, -8.60467152213735e-11f);
    p = fmaf(p, x2,  5.12229709037114e-08f);
    p = fmaf(p, x2,  1.48572235717979e-05f);
    p = fmaf(p, x2,  6.37261928875436e-04f);
    p = fmaf(p, x2,  4.89352455891786e-03f);
    p = p * x;
    float q = fmaf(x2, 1.19825839466702e-06f, 1.18534705686654e-04f);
    q = fmaf(q, x2, 2.26843463243900e-03f);
    qo = fmaf(q, x2, 4.89352518554385e-03f);
    return p;
}

// batched reciprocal: 1 MUFU per 4 divisions
__device__ __forceinline__ void rcp4(const float* q, float* inv)
{
    float a01 = q[0] * q[1], a23 = q[2] * q[3], P = a01 * a23, R;
    asm("rcp.approx.f32 %0, %1;" : "=f"(R) : "f"(P));
    inv[0] = R * q[1] * a23;
    inv[1] = R * q[0] * a23;
    inv[2] = R * a01 * q[3];
    inv[3] = R * a01 * q[2];
}

#define CP_ASYNC16(dst, src) \
    asm volatile("cp.async.cg.shared.global [%0], [%1], 16;" \
                 :: "r"(dst), "l"(src) : "memory")
#define CP_COMMIT() asm volatile("cp.async.commit_group;" ::: "memory")
#define CP_WAIT(n)  asm volatile("cp.async.wait_group %0;" :: "n"(n) : "memory")

// smem (floats): w1s 16384 | w2s 16384 | w3s 4096 | hring 16384 | sp 512 |
//                b1s 128 | b2s 128 | ys 128 | zs 128 | kacc 128 |
//                h1s 128 | h2row 128 | misc 16     (218.7 KB total)
#define SMEM_FLOATS (16384*3 + 4096 + 512 + 7*128 + 16)
#define SMEM_BYTES  (SMEM_FLOATS * 4)

extern __shared__ float smem[];

__global__ __launch_bounds__(NT, 1)
void cde_kernel(const float* __restrict__ coeffs,
                const float* __restrict__ W1, const float* __restrict__ b1,
                const float* __restrict__ W2, const float* __restrict__ b2,
                const float* __restrict__ W3, const float* __restrict__ b3,
                const float* __restrict__ Wi, const float* __restrict__ bi,
                const float* __restrict__ Wr, const float* __restrict__ br,
                float* __restrict__ out)
{
    float* w1s   = smem;                // [k][j]
    float* w2s   = w1s  + 16384;
    float* w3s   = w2s  + 16384;        // [k][c] 128x32 (our h's slice)
    float* hring = w3s  + 4096;         // [k][b] 128x128, 8 stages of 16 k
    float* sp    = hring + 16384;
    float* b1s   = sp   + 512;
    float* b2s   = b1s  + 128;
    float* ys    = b2s  + 128;
    float* zs    = ys   + 128;
    float* kacc  = zs   + 128;
    float* h1s   = kacc + 128;
    float* h2row = h1s  + 128;
    u32* sbase = (u32*)(h2row + 128);

    const int tid = threadIdx.x;
    const int r   = blockIdx.x;         // owned batch row == owned h-slice

    if (tid == 0) {
        u32 g0;
        asm volatile("ld.relaxed.gpu.b32 %0, [%1];" : "=r"(g0) : "l"(&g_gen));
        *sbase = g0;
    }

    // ---- prologue: stage weights into smem ----
    #pragma unroll
    for (int i = 0; i < 8; i++) {
        int idx = tid + i * NT;
        ((float4*)w1s)[idx] = ((const float4*)W1)[idx];
        ((float4*)w2s)[idx] = ((const float4*)W2)[idx];
    }
    #pragma unroll
    for (int i = 0; i < 2; i++) {
        int idx = tid + i * NT;
        int k = idx >> 3, cq = idx & 7;
        *(float4*)(w3s + k * 32 + cq * 4) =
            *(const float4*)(W3 + k * 4096 + r * 32 + cq * 4);
    }
    if (tid < 128) { b1s[tid] = b1[tid]; b2s[tid] = b2[tid]; }

    // z0 = X(0) @ Wi + bi
    if (tid < 128) {
        const float* ca = coeffs + (size_t)r * 8192;
        float acc = bi[tid];
        #pragma unroll
        for (int c = 0; c < 32; c++)
            acc = fmaf(ca[c], Wi[c * 128 + tid], acc);
        zs[tid] = acc; ys[tid] = acc; kacc[tid] = 0.0f;
    }
    __syncthreads();

    const u32 base = *sbase;
    u32 bno = 0;

    // per-thread GEMM constants: 2 rows x 4 cols
    const int cg = tid & 7, rg = tid >> 3;
    const int r0 = rg << 1;
    const float4 b3q = *(const float4*)(b3 + r * 32 + (cg << 2));
    u64 B01, B23;
    asm("mov.b64 %0, {%1,%2};" : "=l"(B01) : "f"(b3q.x), "f"(b3q.y));
    asm("mov.b64 %0, {%1,%2};" : "=l"(B23) : "f"(b3q.z), "f"(b3q.w));
    const float* ws = w3s + (cg << 2);
    u32 hring_a, hdst;
    {
        u64 t = __cvta_generic_to_shared(hring);
        hring_a = (u32)t;                  // base for compute reads
        hdst = (u32)t + (u32)tid * 16;     // this thread's cp.async slot
    }
    const float* hsrc = (const float*)g_h2T + tid * 4;

    for (int s = 0; s < 64; s++) {
        // publish dX for this segment (f=0, f=0.5, f=1)
        if (tid < 32) {
            const float* bc = coeffs + (size_t)r * 8192 + s * 128;
            int c = tid;
            float cb = bc[32 + c], c2 = bc[64 + c], c3 = bc[96 + c];
            g_dx[(r * 3 + 0) * 32 + c] = cb;
            g_dx[(r * 3 + 1) * 32 + c] = fmaf(0.25f, c3, fmaf(0.5f, c2, cb));
            g_dx[(r * 3 + 2) * 32 + c] = (s < 63) ? bc[128 + 32 + c]
                                                  : (cb + c2 + c3);
        }

        for (int stage = 0; stage < 4; stage++) {
            // ---- row-owner: layers 1,2 on own row, publish h2 ----
            gemv128(ys,  w1s, b1s, h1s,   sp);
            gemv128(h1s, w2s, b2s, h2row, sp);
            if (tid < 128)
                g_h2T[tid * 128 + r] = h2row[tid];

            grid_barrier(base + (++bno));   // A: all h2 rows + dX published

            // ---- kick off ALL 8 cp.async stages (16 k x 128 rows each) ----
            #pragma unroll
            for (int st = 0; st < 8; st++) {
                CP_ASYNC16(hdst + st * 8192, hsrc + st * 2048);
                CP_COMMIT();
            }

            // dX loads: L2 latency hides under the first GEMM stages
            const int sel = (stage == 0) ? 0 : ((stage == 3) ? 2 : 1);
            float4 dA = *(const float4*)(g_dx + (r0 * 3 + sel) * 32 + (cg << 2));
            float4 dB = *(const float4*)(g_dx + ((r0 + 1) * 3 + sel) * 32 + (cg << 2));

            // ---- GEMM: consume ring stages, FFMA2 ----
            u64 A01 = B01, A23 = B23;   // row r0,   cols (0,1) (2,3)
            u64 E01 = B01, E23 = B23;   // row r0+1
            #define GSTAGE(BB)                                                       \
            {   CP_WAIT(7 - (BB));                                                   \
                __syncthreads();                                                     \
                const float* hb = hring + (BB) * 2048 + r0;                          \
                const float* wb = ws + (BB) * 512;                                   \
                _Pragma("unroll")                                                    \
                for (int kk = 0; kk < 16; kk++) {                                    \
                    float2 h = *(const float2*)(hb + kk * 128);                      \
                    float4 w = *(const float4*)(wb + kk * 32);                       \
                    u64 w01, w23, hx2, hy2;                                          \
                    asm("mov.b64 %0, {%1,%2};" : "=l"(w01) : "f"(w.x), "f"(w.y));    \
                    asm("mov.b64 %0, {%1,%2};" : "=l"(w23) : "f"(w.z), "f"(w.w));    \
                    asm("mov.b64 %0, {%1,%1};" : "=l"(hx2) : "f"(h.x));              \
                    asm("mov.b64 %0, {%1,%1};" : "=l"(hy2) : "f"(h.y));              \
                    asm("fma.rn.f32x2 %0,%1,%2,%0;" : "+l"(A01) : "l"(w01), "l"(hx2)); \
                    asm("fma.rn.f32x2 %0,%1,%2,%0;" : "+l"(A23) : "l"(w23), "l"(hx2)); \
                    asm("fma.rn.f32x2 %0,%1,%2,%0;" : "+l"(E01) : "l"(w01), "l"(hy2)); \
                    asm("fma.rn.f32x2 %0,%1,%2,%0;" : "+l"(E23) : "l"(w23), "l"(hy2)); \
                }                                                                    \
            }
            GSTAGE(0) GSTAGE(1) GSTAGE(2) GSTAGE(3)
            GSTAGE(4) GSTAGE(5) GSTAGE(6) GSTAGE(7)
            #undef GSTAGE

            float a0, a1, a2, a3, e0, e1, e2, e3;
            asm("mov.b64 {%0,%1}, %2;" : "=f"(a0), "=f"(a1) : "l"(A01));
            asm("mov.b64 {%0,%1}, %2;" : "=f"(a2), "=f"(a3) : "l"(A23));
            asm("mov.b64 {%0,%1}, %2;" : "=f"(e0), "=f"(e1) : "l"(E01));
            asm("mov.b64 {%0,%1}, %2;" : "=f"(e2), "=f"(e3) : "l"(E23));

            // ---- tanh (rational, batched rcp) + contraction with dX ----
            float p[8], q[8], inv[8];
            p[0] = tanh_pq(a0, q[0]); p[1] = tanh_pq(a1, q[1]);
            p[2] = tanh_pq(a2, q[2]); p[3] = tanh_pq(a3, q[3]);
            p[4] = tanh_pq(e0, q[4]); p[5] = tanh_pq(e1, q[5]);
            p[6] = tanh_pq(e2, q[6]); p[7] = tanh_pq(e3, q[7]);
            rcp4(q,     inv);
            rcp4(q + 4, inv + 4);

            float pr0 = p[0]*inv[0]*dA.x + p[1]*inv[1]*dA.y
                      + p[2]*inv[2]*dA.z + p[3]*inv[3]*dA.w;
            float pr1 = p[4]*inv[4]*dB.x + p[5]*inv[5]*dB.y
                      + p[6]*inv[6]*dB.z + p[7]*inv[7]*dB.w;
            #pragma unroll
            for (int off = 4; off >= 1; off >>= 1) {
                pr0 += __shfl_down_sync(0xffffffffu, pr0, off);
                pr1 += __shfl_down_sync(0xffffffffu, pr1, off);
            }
            if (cg == 0) {
                g_dz[ r0      * 128 + r] = pr0;
                g_dz[(r0 + 1) * 128 + r] = pr1;
            }

            grid_barrier(base + (++bno));   // B: dz complete

            // ---- row-owner: RK4 stage update ----
            if (tid < 32) {
                int h0 = tid << 2;
                float4 dz = *(const float4*)(g_dz + r * 128 + h0);
                float4 kq = *(float4*)(kacc + h0);
                float4 zq = *(float4*)(zs + h0);
                float kw = (stage == 0 || stage == 3) ? 1.0f : 2.0f;
                kq.x = fmaf(kw, dz.x, kq.x); kq.y = fmaf(kw, dz.y, kq.y);
                kq.z = fmaf(kw, dz.z, kq.z); kq.w = fmaf(kw, dz.w, kq.w);
                if (stage < 3) {
                    float aa = (stage == 2) ? 1.0f : 0.5f;
                    float4 yq;
                    yq.x = fmaf(aa, dz.x, zq.x); yq.y = fmaf(aa, dz.y, zq.y);
                    yq.z = fmaf(aa, dz.z, zq.z); yq.w = fmaf(aa, dz.w, zq.w);
                    *(float4*)(ys + h0) = yq;
                    *(float4*)(kacc + h0) = kq;
                } else {
                    const float c6 = 1.0f / 6.0f;
                    zq.x = fmaf(c6, kq.x, zq.x); zq.y = fmaf(c6, kq.y, zq.y);
                    zq.z = fmaf(c6, kq.z, zq.z); zq.w = fmaf(c6, kq.w, zq.w);
                    *(float4*)(zs + h0) = zq;
                    *(float4*)(ys + h0) = zq;
                    *(float4*)(kacc + h0) = make_float4(0.f, 0.f, 0.f, 0.f);
                }
            }
            __syncthreads();
        }
    }

    // ---- readout: out[r] = sigmoid(z @ Wr + br) ----
    if (tid < 32) {
        float part = 0.0f;
        #pragma unroll
        for (int h = tid; h < 128; h += 32)
            part = fmaf(zs[h], Wr[h], part);
        #pragma unroll
        for (int off = 16; off >= 1; off >>= 1)
            part += __shfl_down_sync(0xffffffffu, part, off);
        if (tid == 0)
            out[r] = 1.0f / (1.0f + __expf(-(part + br[0])));
    }
}

extern "C" void kernel_launch(void* const* d_in, const int* in_sizes, int n_in,
                              void* d_out, int out_size)
{
    const float* coeffs = (const float*)d_in[0];
    const float* W1 = (const float*)d_in[1];
    const float* b1 = (const float*)d_in[2];
    const float* W2 = (const float*)d_in[3];
    const float* b2 = (const float*)d_in[4];
    const float* W3 = (const float*)d_in[5];
    const float* b3 = (const float*)d_in[6];
    const float* Wi = (const float*)d_in[7];
    const float* bi = (const float*)d_in[8];
    const float* Wr = (const float*)d_in[9];
    const float* br = (const float*)d_in[10];
    float* out = (float*)d_out;

    cudaFuncSetAttribute(cde_kernel,
                         cudaFuncAttributeMaxDynamicSharedMemorySize, SMEM_BYTES);
    cde_kernel<<<NCTAS, NT, SMEM_BYTES>>>(coeffs, W1, b1, W2, b2, W3, b3,
                                          Wi, bi, Wr, br, out);
}